// round 1
// baseline (speedup 1.0000x reference)
#include <cuda_runtime.h>
#include <cuda_bf16.h>
#include <math.h>

// Problem constants
#define BATCH   32
#define HRES    64
#define WRES    64
#define DIM     192
#define C3      576
#define HID     768
#define NHEAD   6
#define HD      32
#define WS      8
#define MTOK    (BATCH * HRES * WRES)   // 131072 rows
#define NWIN    (MTOK / 64)             // 2048 windows
#define QSCALE  0.17677669529663687f    // 1/sqrt(32)

// ---------------- static scratch (allocation-free rule) ----------------
__device__ float g_ln  [(size_t)MTOK * DIM];   // LN1 / LN2 output
__device__ float g_qkv [(size_t)MTOK * C3];    // window-ordered qkv
__device__ float g_attn[(size_t)MTOK * DIM];   // window-ordered attn out
__device__ float g_x2  [(size_t)MTOK * DIM];   // x + attn branch (orig order)
__device__ float g_mlp [(size_t)MTOK * HID];   // gelu(fc1) output

// window-ordered row -> original row
__device__ __forceinline__ int orig_row(int wr) {
    int b  = wr >> 12;          // image
    int r  = wr & 4095;
    int wb = r >> 6;            // window within image (0..63)
    int n  = r & 63;            // position within window
    int hh = ((wb >> 3) << 3) + (n >> 3);
    int ww = ((wb & 7) << 3) + (n & 7);
    return (b << 12) + (hh << 6) + ww;
}

// ---------------- LayerNorm: one warp per row of 192 ----------------
template<bool FROM_X2>
__global__ void ln_kernel(const float* __restrict__ xin,
                          const float* __restrict__ gamma,
                          const float* __restrict__ beta) {
    int warp = (blockIdx.x * blockDim.x + threadIdx.x) >> 5;
    int lane = threadIdx.x & 31;
    if (warp >= MTOK) return;
    const float* src = FROM_X2 ? g_x2 : xin;
    const float* row = src + (size_t)warp * DIM;
    float v[6];
    float s = 0.f, s2 = 0.f;
#pragma unroll
    for (int i = 0; i < 6; i++) {
        v[i] = row[lane + i * 32];
        s  += v[i];
        s2 += v[i] * v[i];
    }
#pragma unroll
    for (int off = 16; off > 0; off >>= 1) {
        s  += __shfl_xor_sync(0xffffffff, s,  off);
        s2 += __shfl_xor_sync(0xffffffff, s2, off);
    }
    float mean = s * (1.0f / DIM);
    float var  = s2 * (1.0f / DIM) - mean * mean;
    float rs   = rsqrtf(var + 1e-5f);
    float* dst = g_ln + (size_t)warp * DIM;
#pragma unroll
    for (int i = 0; i < 6; i++) {
        int c = lane + i * 32;
        dst[c] = (v[i] - mean) * rs * gamma[c] + beta[c];
    }
}

// ---------------- Tiled SGEMM, 64x64x16, 4x4 microtile ----------------
// MODE 0: qkv  = gather(g_ln by window perm) @ qkv_w + b ; scale q cols -> g_qkv
// MODE 1: x2   = scatter(g_attn @ proj_w + b) + x        -> g_x2 (orig order)
// MODE 2: mlp  = gelu(g_ln @ fc1_w + b)                  -> g_mlp
// MODE 3: out  = g_mlp @ fc2_w + b + g_x2                -> d_out
template<int MODE, int K, int N>
__global__ void gemm_kernel(const float* __restrict__ Bw,
                            const float* __restrict__ bias,
                            const float* __restrict__ extra,
                            float* __restrict__ outp) {
    const float* A;
    if (MODE == 0 || MODE == 2) A = g_ln;
    else if (MODE == 1)          A = g_attn;
    else                         A = g_mlp;

    __shared__ float As[16][64];
    __shared__ float Bs[16][64];

    int tid = threadIdx.x;               // 256 threads
    int aM  = tid >> 2;                  // 0..63
    int aK4 = (tid & 3) << 2;            // 0,4,8,12
    int bK  = tid >> 4;                  // 0..15
    int bN4 = (tid & 15) << 2;           // 0..60

    int rowBase = blockIdx.y << 6;
    int colBase = blockIdx.x << 6;

    int arow = rowBase + aM;             // window-ordered index for MODE 0 output
    int grow = (MODE == 0) ? orig_row(arow) : arow;
    const float* aptr = A + (size_t)grow * K;
    const float* bptr = Bw + colBase;

    float acc[4][4] = {};

    for (int kt = 0; kt < K; kt += 16) {
        float4 av = *(const float4*)(aptr + kt + aK4);
        As[aK4 + 0][aM] = av.x;
        As[aK4 + 1][aM] = av.y;
        As[aK4 + 2][aM] = av.z;
        As[aK4 + 3][aM] = av.w;
        float4 bv = *(const float4*)(bptr + (size_t)(kt + bK) * N + bN4);
        *(float4*)&Bs[bK][bN4] = bv;
        __syncthreads();
#pragma unroll
        for (int k = 0; k < 16; k++) {
            float4 a = *(const float4*)&As[k][(tid >> 4) << 2];
            float4 b = *(const float4*)&Bs[k][(tid & 15) << 2];
            float ar[4] = {a.x, a.y, a.z, a.w};
            float br[4] = {b.x, b.y, b.z, b.w};
#pragma unroll
            for (int i = 0; i < 4; i++)
#pragma unroll
                for (int j = 0; j < 4; j++)
                    acc[i][j] = fmaf(ar[i], br[j], acc[i][j]);
        }
        __syncthreads();
    }

    int ty = tid >> 4, tx = tid & 15;
#pragma unroll
    for (int i = 0; i < 4; i++) {
        int m = rowBase + ty * 4 + i;
        int om;
        if (MODE == 1) om = orig_row(m);
#pragma unroll
        for (int j = 0; j < 4; j++) {
            int n = colBase + tx * 4 + j;
            float v = acc[i][j] + bias[n];
            if (MODE == 0) {
                if (n < DIM) v *= QSCALE;                  // fold q scaling
                g_qkv[(size_t)m * C3 + n] = v;
            } else if (MODE == 1) {
                g_x2[(size_t)om * DIM + n] = extra[(size_t)om * DIM + n] + v;
            } else if (MODE == 2) {
                g_mlp[(size_t)m * HID + n] =
                    0.5f * v * (1.0f + erff(v * 0.70710678118654752f));
            } else {
                outp[(size_t)m * DIM + n] = v + g_x2[(size_t)m * DIM + n];
            }
        }
    }
}

// ---------------- attention: one block per (window, head) ----------------
// N=64 queries, hd=32. 64 threads, thread t owns query t.
__global__ void attn_kernel() {
    __shared__ float sq[64 * 32];
    __shared__ float sk[64 * 32];
    __shared__ float sv[64 * 32];
    __shared__ float sp[64 * 65];   // padded scores

    int win  = blockIdx.x / NHEAD;
    int head = blockIdx.x % NHEAD;
    int tid  = threadIdx.x;   // 0..63

    const float* base = g_qkv + (size_t)win * 64 * C3;
    int qoff = head * HD;
    int koff = DIM + head * HD;
    int voff = 2 * DIM + head * HD;

    for (int idx = tid; idx < 64 * 32; idx += 64) {
        int n = idx >> 5, d = idx & 31;
        sq[idx] = base[n * C3 + qoff + d];
        sk[idx] = base[n * C3 + koff + d];
        sv[idx] = base[n * C3 + voff + d];
    }
    __syncthreads();

    float qr[32];
#pragma unroll
    for (int d = 0; d < 32; d++) qr[d] = sq[tid * 32 + d];

    float mx = -1e30f;
    for (int j = 0; j < 64; j++) {
        float s = 0.f;
#pragma unroll
        for (int d = 0; d < 32; d++) s = fmaf(qr[d], sk[j * 32 + d], s);
        sp[tid * 65 + j] = s;
        mx = fmaxf(mx, s);
    }
    float sum = 0.f;
    for (int j = 0; j < 64; j++) {
        float e = __expf(sp[tid * 65 + j] - mx);
        sp[tid * 65 + j] = e;
        sum += e;
    }
    float inv = 1.0f / sum;

    float o[32] = {};
    for (int j = 0; j < 64; j++) {
        float p = sp[tid * 65 + j];
#pragma unroll
        for (int d = 0; d < 32; d++) o[d] = fmaf(p, sv[j * 32 + d], o[d]);
    }

    __syncthreads();   // done reading sq
#pragma unroll
    for (int d = 0; d < 32; d++) sq[tid * 32 + d] = o[d] * inv;
    __syncthreads();

    float* obase = g_attn + (size_t)win * 64 * DIM + head * HD;
    for (int idx = tid; idx < 64 * 32; idx += 64) {
        int n = idx >> 5, d = idx & 31;
        obase[n * DIM + d] = sq[idx];
    }
}

// ---------------- launcher ----------------
extern "C" void kernel_launch(void* const* d_in, const int* in_sizes, int n_in,
                              void* d_out, int out_size) {
    const float* x       = (const float*)d_in[0];
    const float* norm1_g = (const float*)d_in[1];
    const float* norm1_b = (const float*)d_in[2];
    const float* qkv_w   = (const float*)d_in[3];
    const float* qkv_b   = (const float*)d_in[4];
    const float* proj_w  = (const float*)d_in[5];
    const float* proj_b  = (const float*)d_in[6];
    const float* norm2_g = (const float*)d_in[7];
    const float* norm2_b = (const float*)d_in[8];
    const float* fc1_w   = (const float*)d_in[9];
    const float* fc1_b   = (const float*)d_in[10];
    const float* fc2_w   = (const float*)d_in[11];
    const float* fc2_b   = (const float*)d_in[12];
    float* out = (float*)d_out;

    // 1. LN1
    ln_kernel<false><<<MTOK / 8, 256>>>(x, norm1_g, norm1_b);
    // 2. QKV (window gather + q scale)
    gemm_kernel<0, DIM, C3><<<dim3(C3 / 64, MTOK / 64), 256>>>(qkv_w, qkv_b, nullptr, nullptr);
    // 3. windowed attention
    attn_kernel<<<NWIN * NHEAD, 64>>>();
    // 4. proj + window reverse + residual
    gemm_kernel<1, DIM, DIM><<<dim3(DIM / 64, MTOK / 64), 256>>>(proj_w, proj_b, x, nullptr);
    // 5. LN2
    ln_kernel<true><<<MTOK / 8, 256>>>(nullptr, norm2_g, norm2_b);
    // 6. FC1 + GELU
    gemm_kernel<2, DIM, HID><<<dim3(HID / 64, MTOK / 64), 256>>>(fc1_w, fc1_b, nullptr, nullptr);
    // 7. FC2 + residual -> out
    gemm_kernel<3, HID, DIM><<<dim3(DIM / 64, MTOK / 64), 256>>>(fc2_w, fc2_b, nullptr, out);
}

// round 2
// speedup vs baseline: 2.1909x; 2.1909x over previous
#include <cuda_runtime.h>
#include <cuda_bf16.h>
#include <math.h>
#include <stdint.h>

// Problem constants
#define BATCH   32
#define HRES    64
#define WRES    64
#define DIM     192
#define C3      576
#define HID     768
#define NHEAD   6
#define HD      32
#define WS      8
#define MTOK    (BATCH * HRES * WRES)   // 131072 rows
#define NWIN    (MTOK / 64)             // 2048 windows
#define QSCALE  0.17677669529663687f    // 1/sqrt(32)

// ---------------- static scratch (allocation-free rule) ----------------
__device__ float g_ln  [(size_t)MTOK * DIM];   // LN1 / LN2 output
__device__ float g_qkv [(size_t)MTOK * C3];    // window-ordered qkv
__device__ float g_attn[(size_t)MTOK * DIM];   // window-ordered attn out
__device__ float g_x2  [(size_t)MTOK * DIM];   // x + attn branch (orig order)
__device__ float g_mlp [(size_t)MTOK * HID];   // gelu(fc1) output

// window-ordered row -> original row
__device__ __forceinline__ int orig_row(int wr) {
    int b  = wr >> 12;          // image
    int r  = wr & 4095;
    int wb = r >> 6;            // window within image (0..63)
    int n  = r & 63;            // position within window
    int hh = ((wb >> 3) << 3) + (n >> 3);
    int ww = ((wb & 7) << 3) + (n & 7);
    return (b << 12) + (hh << 6) + ww;
}

__device__ __forceinline__ uint32_t f2tf32(float f) {
    uint32_t u;
    asm("cvt.rna.tf32.f32 %0, %1;" : "=r"(u) : "f"(f));
    return u;
}

__device__ __forceinline__ void mma_tf32(float c[4], const uint32_t a[4], const uint32_t b[2]) {
    asm volatile(
        "mma.sync.aligned.m16n8k8.row.col.f32.tf32.tf32.f32 "
        "{%0,%1,%2,%3}, {%4,%5,%6,%7}, {%8,%9}, {%0,%1,%2,%3};"
        : "+f"(c[0]), "+f"(c[1]), "+f"(c[2]), "+f"(c[3])
        : "r"(a[0]), "r"(a[1]), "r"(a[2]), "r"(a[3]), "r"(b[0]), "r"(b[1]));
}

// ---------------- LayerNorm: one warp per row of 192 ----------------
template<bool FROM_X2>
__global__ void ln_kernel(const float* __restrict__ xin,
                          const float* __restrict__ gamma,
                          const float* __restrict__ beta) {
    int warp = (blockIdx.x * blockDim.x + threadIdx.x) >> 5;
    int lane = threadIdx.x & 31;
    if (warp >= MTOK) return;
    const float* src = FROM_X2 ? g_x2 : xin;
    const float* row = src + (size_t)warp * DIM;
    float v[6];
    float s = 0.f, s2 = 0.f;
#pragma unroll
    for (int i = 0; i < 6; i++) {
        v[i] = row[lane + i * 32];
        s  += v[i];
        s2 += v[i] * v[i];
    }
#pragma unroll
    for (int off = 16; off > 0; off >>= 1) {
        s  += __shfl_xor_sync(0xffffffff, s,  off);
        s2 += __shfl_xor_sync(0xffffffff, s2, off);
    }
    float mean = s * (1.0f / DIM);
    float var  = s2 * (1.0f / DIM) - mean * mean;
    float rs   = rsqrtf(var + 1e-5f);
    float* dst = g_ln + (size_t)warp * DIM;
#pragma unroll
    for (int i = 0; i < 6; i++) {
        int c = lane + i * 32;
        dst[c] = (v[i] - mean) * rs * gamma[c] + beta[c];
    }
}

// ---------------- TF32 tensor-core GEMM, 128x64x32 block tile ----------------
// 8 warps (4M x 2N), warp tile 32x32, mma.m16n8k8.
// MODE 0: qkv  = gather(g_ln by window perm) @ qkv_w + b ; scale q cols -> g_qkv
// MODE 1: x2   = scatter(g_attn @ proj_w + b) + x        -> g_x2 (orig order)
// MODE 2: mlp  = gelu(g_ln @ fc1_w + b)                  -> g_mlp
// MODE 3: out  = g_mlp @ fc2_w + b + g_x2                -> d_out
#define AS_STRIDE 36   // (4*row+col)%32 -> conflict-free a-frag reads
#define BS_STRIDE 72   // (8*k+n)%32   -> conflict-free b-frag reads

template<int MODE, int K, int N>
__global__ __launch_bounds__(256)
void gemm_tc(const float* __restrict__ Bw,
             const float* __restrict__ bias,
             const float* __restrict__ extra,
             float* __restrict__ outp) {
    const float* A;
    if (MODE == 0 || MODE == 2) A = g_ln;
    else if (MODE == 1)          A = g_attn;
    else                         A = g_mlp;

    __shared__ uint32_t As[128 * AS_STRIDE];
    __shared__ uint32_t Bs[32 * BS_STRIDE];

    int tid   = threadIdx.x;
    int lane  = tid & 31;
    int warp  = tid >> 5;
    int warpM = warp >> 1;        // 0..3
    int warpN = warp & 1;         // 0..1
    int rowBase = blockIdx.y << 7;    // *128
    int colBase = blockIdx.x << 6;    // *64

    // staging indices: A = 128x32 (4 float4/thread), B = 32x64 (2 float4/thread)
    int aR  = tid >> 3;                // 0..31 (plus i*32)
    int aC4 = (tid & 7) << 2;          // 0,4,...,28
    int bK  = tid >> 4;                // 0..15 (plus i*16)
    int bN4 = (tid & 15) << 2;         // 0..60

    // precompute gathered row indices for A staging
    int gRow[4];
#pragma unroll
    for (int i = 0; i < 4; i++) {
        int r = rowBase + aR + i * 32;
        gRow[i] = (MODE == 0) ? orig_row(r) : r;
    }

    float acc[2][4][4] = {};

    for (int kt = 0; kt < K; kt += 32) {
#pragma unroll
        for (int i = 0; i < 4; i++) {
            float4 v = *(const float4*)(A + (size_t)gRow[i] * K + kt + aC4);
            uint32_t* d = &As[(aR + i * 32) * AS_STRIDE + aC4];
            d[0] = f2tf32(v.x); d[1] = f2tf32(v.y);
            d[2] = f2tf32(v.z); d[3] = f2tf32(v.w);
        }
#pragma unroll
        for (int i = 0; i < 2; i++) {
            int k = bK + i * 16;
            float4 v = *(const float4*)(Bw + (size_t)(kt + k) * N + colBase + bN4);
            uint32_t* d = &Bs[k * BS_STRIDE + bN4];
            d[0] = f2tf32(v.x); d[1] = f2tf32(v.y);
            d[2] = f2tf32(v.z); d[3] = f2tf32(v.w);
        }
        __syncthreads();

#pragma unroll
        for (int k8 = 0; k8 < 4; k8++) {
            uint32_t a[2][4], b[4][2];
            int ar = (warpM << 5) + (lane >> 2);
            int ac = (k8 << 3) + (lane & 3);
#pragma unroll
            for (int mt = 0; mt < 2; mt++) {
                int r = ar + mt * 16;
                a[mt][0] = As[r * AS_STRIDE + ac];
                a[mt][1] = As[(r + 8) * AS_STRIDE + ac];
                a[mt][2] = As[r * AS_STRIDE + ac + 4];
                a[mt][3] = As[(r + 8) * AS_STRIDE + ac + 4];
            }
            int bn = (warpN << 5) + (lane >> 2);
            int bk = (k8 << 3) + (lane & 3);
#pragma unroll
            for (int nt = 0; nt < 4; nt++) {
                b[nt][0] = Bs[bk * BS_STRIDE + bn + nt * 8];
                b[nt][1] = Bs[(bk + 4) * BS_STRIDE + bn + nt * 8];
            }
#pragma unroll
            for (int mt = 0; mt < 2; mt++)
#pragma unroll
                for (int nt = 0; nt < 4; nt++)
                    mma_tf32(acc[mt][nt], a[mt], b[nt]);
        }
        __syncthreads();
    }

    // ---------------- epilogue ----------------
    int rBase = rowBase + (warpM << 5) + (lane >> 2);
    int cBase = colBase + (warpN << 5) + ((lane & 3) << 1);
#pragma unroll
    for (int mt = 0; mt < 2; mt++) {
#pragma unroll
        for (int half = 0; half < 2; half++) {          // c0/c1 vs c2/c3 (row+8)
            int m = rBase + mt * 16 + half * 8;
            int om = m;
            if (MODE == 1) om = orig_row(m);
#pragma unroll
            for (int nt = 0; nt < 4; nt++) {
#pragma unroll
                for (int j = 0; j < 2; j++) {
                    int n = cBase + nt * 8 + j;
                    float v = acc[mt][nt][half * 2 + j] + bias[n];
                    if (MODE == 0) {
                        if (n < DIM) v *= QSCALE;
                        g_qkv[(size_t)m * C3 + n] = v;
                    } else if (MODE == 1) {
                        g_x2[(size_t)om * DIM + n] = extra[(size_t)om * DIM + n] + v;
                    } else if (MODE == 2) {
                        g_mlp[(size_t)m * HID + n] =
                            0.5f * v * (1.0f + erff(v * 0.70710678118654752f));
                    } else {
                        outp[(size_t)m * DIM + n] = v + g_x2[(size_t)m * DIM + n];
                    }
                }
            }
        }
    }
}

// ---------------- attention: one block per (window, head) ----------------
__global__ void attn_kernel() {
    __shared__ float sq[64 * 32];
    __shared__ float sk[64 * 32];
    __shared__ float sv[64 * 32];
    __shared__ float sp[64 * 65];

    int win  = blockIdx.x / NHEAD;
    int head = blockIdx.x % NHEAD;
    int tid  = threadIdx.x;   // 0..63

    const float* base = g_qkv + (size_t)win * 64 * C3;
    int qoff = head * HD;
    int koff = DIM + head * HD;
    int voff = 2 * DIM + head * HD;

    for (int idx = tid; idx < 64 * 32; idx += 64) {
        int n = idx >> 5, d = idx & 31;
        sq[idx] = base[n * C3 + qoff + d];
        sk[idx] = base[n * C3 + koff + d];
        sv[idx] = base[n * C3 + voff + d];
    }
    __syncthreads();

    float qr[32];
#pragma unroll
    for (int d = 0; d < 32; d++) qr[d] = sq[tid * 32 + d];

    float mx = -1e30f;
    for (int j = 0; j < 64; j++) {
        float s = 0.f;
#pragma unroll
        for (int d = 0; d < 32; d++) s = fmaf(qr[d], sk[j * 32 + d], s);
        sp[tid * 65 + j] = s;
        mx = fmaxf(mx, s);
    }
    float sum = 0.f;
    for (int j = 0; j < 64; j++) {
        float e = __expf(sp[tid * 65 + j] - mx);
        sp[tid * 65 + j] = e;
        sum += e;
    }
    float inv = 1.0f / sum;

    float o[32] = {};
    for (int j = 0; j < 64; j++) {
        float p = sp[tid * 65 + j];
#pragma unroll
        for (int d = 0; d < 32; d++) o[d] = fmaf(p, sv[j * 32 + d], o[d]);
    }

    __syncthreads();
#pragma unroll
    for (int d = 0; d < 32; d++) sq[tid * 32 + d] = o[d] * inv;
    __syncthreads();

    float* obase = g_attn + (size_t)win * 64 * DIM + head * HD;
    for (int idx = tid; idx < 64 * 32; idx += 64) {
        int n = idx >> 5, d = idx & 31;
        obase[n * DIM + d] = sq[idx];
    }
}

// ---------------- launcher ----------------
extern "C" void kernel_launch(void* const* d_in, const int* in_sizes, int n_in,
                              void* d_out, int out_size) {
    const float* x       = (const float*)d_in[0];
    const float* norm1_g = (const float*)d_in[1];
    const float* norm1_b = (const float*)d_in[2];
    const float* qkv_w   = (const float*)d_in[3];
    const float* qkv_b   = (const float*)d_in[4];
    const float* proj_w  = (const float*)d_in[5];
    const float* proj_b  = (const float*)d_in[6];
    const float* norm2_g = (const float*)d_in[7];
    const float* norm2_b = (const float*)d_in[8];
    const float* fc1_w   = (const float*)d_in[9];
    const float* fc1_b   = (const float*)d_in[10];
    const float* fc2_w   = (const float*)d_in[11];
    const float* fc2_b   = (const float*)d_in[12];
    float* out = (float*)d_out;

    // 1. LN1
    ln_kernel<false><<<MTOK / 8, 256>>>(x, norm1_g, norm1_b);
    // 2. QKV (window gather + q scale)
    gemm_tc<0, DIM, C3><<<dim3(C3 / 64, MTOK / 128), 256>>>(qkv_w, qkv_b, nullptr, nullptr);
    // 3. windowed attention
    attn_kernel<<<NWIN * NHEAD, 64>>>();
    // 4. proj + window reverse + residual
    gemm_tc<1, DIM, DIM><<<dim3(DIM / 64, MTOK / 128), 256>>>(proj_w, proj_b, x, nullptr);
    // 5. LN2
    ln_kernel<true><<<MTOK / 8, 256>>>(nullptr, norm2_g, norm2_b);
    // 6. FC1 + GELU
    gemm_tc<2, DIM, HID><<<dim3(HID / 64, MTOK / 128), 256>>>(fc1_w, fc1_b, nullptr, nullptr);
    // 7. FC2 + residual -> out
    gemm_tc<3, HID, DIM><<<dim3(DIM / 64, MTOK / 128), 256>>>(fc2_w, fc2_b, nullptr, out);
}

// round 3
// speedup vs baseline: 2.4411x; 1.1142x over previous
#include <cuda_runtime.h>
#include <cuda_bf16.h>
#include <math.h>
#include <stdint.h>

// Problem constants
#define BATCH   32
#define HRES    64
#define WRES    64
#define DIM     192
#define C3      576
#define HID     768
#define NHEAD   6
#define HD      32
#define WS      8
#define MTOK    (BATCH * HRES * WRES)   // 131072 rows
#define NWIN    (MTOK / 64)             // 2048 windows
#define QSCALE  0.17677669529663687f    // 1/sqrt(32)

// ---------------- static scratch (allocation-free rule) ----------------
__device__ float g_ln  [(size_t)MTOK * DIM];
__device__ float g_qkv [(size_t)MTOK * C3];
__device__ float g_attn[(size_t)MTOK * DIM];
__device__ float g_x2  [(size_t)MTOK * DIM];
__device__ float g_mlp [(size_t)MTOK * HID];

__device__ __forceinline__ int orig_row(int wr) {
    int b  = wr >> 12;
    int r  = wr & 4095;
    int wb = r >> 6;
    int n  = r & 63;
    int hh = ((wb >> 3) << 3) + (n >> 3);
    int ww = ((wb & 7) << 3) + (n & 7);
    return (b << 12) + (hh << 6) + ww;
}

__device__ __forceinline__ uint32_t f2tf32(float f) {
    uint32_t u;
    asm("cvt.rna.tf32.f32 %0, %1;" : "=r"(u) : "f"(f));
    return u;
}

__device__ __forceinline__ void mma_tf32(float c[4], const uint32_t a[4], const uint32_t b[2]) {
    asm volatile(
        "mma.sync.aligned.m16n8k8.row.col.f32.tf32.tf32.f32 "
        "{%0,%1,%2,%3}, {%4,%5,%6,%7}, {%8,%9}, {%0,%1,%2,%3};"
        : "+f"(c[0]), "+f"(c[1]), "+f"(c[2]), "+f"(c[3])
        : "r"(a[0]), "r"(a[1]), "r"(a[2]), "r"(a[3]), "r"(b[0]), "r"(b[1]));
}

#define CP16(dst_u32, src_ptr) \
    asm volatile("cp.async.cg.shared.global [%0], [%1], 16;" :: "r"(dst_u32), "l"(src_ptr))
#define CP_COMMIT() asm volatile("cp.async.commit_group;")
#define CP_WAIT(n)  asm volatile("cp.async.wait_group %0;" :: "n"(n))

// ---------------- LayerNorm: one warp per row of 192 ----------------
template<bool FROM_X2>
__global__ void ln_kernel(const float* __restrict__ xin,
                          const float* __restrict__ gamma,
                          const float* __restrict__ beta) {
    int warp = (blockIdx.x * blockDim.x + threadIdx.x) >> 5;
    int lane = threadIdx.x & 31;
    if (warp >= MTOK) return;
    const float* src = FROM_X2 ? g_x2 : xin;
    const float* row = src + (size_t)warp * DIM;
    float v[6];
    float s = 0.f, s2 = 0.f;
#pragma unroll
    for (int i = 0; i < 6; i++) {
        v[i] = row[lane + i * 32];
        s  += v[i];
        s2 += v[i] * v[i];
    }
#pragma unroll
    for (int off = 16; off > 0; off >>= 1) {
        s  += __shfl_xor_sync(0xffffffff, s,  off);
        s2 += __shfl_xor_sync(0xffffffff, s2, off);
    }
    float mean = s * (1.0f / DIM);
    float var  = s2 * (1.0f / DIM) - mean * mean;
    float rs   = rsqrtf(var + 1e-5f);
    float* dst = g_ln + (size_t)warp * DIM;
#pragma unroll
    for (int i = 0; i < 6; i++) {
        int c = lane + i * 32;
        dst[c] = (v[i] - mean) * rs * gamma[c] + beta[c];
    }
}

// ---------------- TF32 TC GEMM, 128x64x32 tile, cp.async double buffer ----
#define AS_STRIDE 36   // floats per A row slab (32 + 4 pad)
#define BS_STRIDE 72   // floats per B row slab (64 + 8 pad)
#define ABUF_F    (128 * AS_STRIDE)            // 4608
#define BBUF_F    (32 * BS_STRIDE)             // 2304
#define STAGE_F   (ABUF_F + BBUF_F)            // 6912 floats per stage

template<int MODE, int K, int N>
__global__ __launch_bounds__(256)
void gemm_tc(const float* __restrict__ Bw,
             const float* __restrict__ bias,
             const float* __restrict__ extra,
             float* __restrict__ outp) {
    const float* A;
    if (MODE == 0 || MODE == 2) A = g_ln;
    else if (MODE == 1)          A = g_attn;
    else                         A = g_mlp;

    __shared__ float smem[2 * STAGE_F];

    int tid   = threadIdx.x;
    int lane  = tid & 31;
    int warp  = tid >> 5;
    int warpM = warp >> 1;
    int warpN = warp & 1;
    int rowBase = blockIdx.y << 7;
    int colBase = blockIdx.x << 6;

    // staging indices
    int aR  = tid >> 3;                // 0..31 (+32i)
    int aC4 = (tid & 7) << 2;          // 0,4..28
    int bK  = tid >> 4;                // 0..15 (+16i)
    int bN4 = (tid & 15) << 2;         // 0..60

    const float* aSrc[4];
#pragma unroll
    for (int i = 0; i < 4; i++) {
        int r = rowBase + aR + i * 32;
        int g = (MODE == 0) ? orig_row(r) : r;
        aSrc[i] = A + (size_t)g * K + aC4;
    }
    const float* bSrc = Bw + (size_t)bK * N + colBase + bN4;

    uint32_t sBase = (uint32_t)__cvta_generic_to_shared(smem);
    uint32_t aDst[4], bDst[2];
#pragma unroll
    for (int i = 0; i < 4; i++)
        aDst[i] = sBase + ((aR + i * 32) * AS_STRIDE + aC4) * 4;
#pragma unroll
    for (int i = 0; i < 2; i++)
        bDst[i] = sBase + (ABUF_F + (bK + i * 16) * BS_STRIDE + bN4) * 4;

    const int NT = K / 32;
    float acc[2][4][4] = {};

    // prologue: stage 0
    {
#pragma unroll
        for (int i = 0; i < 4; i++) CP16(aDst[i], aSrc[i]);
#pragma unroll
        for (int i = 0; i < 2; i++) CP16(bDst[i], bSrc + (size_t)(i * 16) * N);
        CP_COMMIT();
    }

    for (int t = 0; t < NT; t++) {
        int buf = t & 1;
        if (t + 1 < NT) {
            int nb = buf ^ 1;
            uint32_t off = nb * STAGE_F * 4;
            int kt = (t + 1) * 32;
#pragma unroll
            for (int i = 0; i < 4; i++) CP16(aDst[i] + off, aSrc[i] + kt);
#pragma unroll
            for (int i = 0; i < 2; i++)
                CP16(bDst[i] + off, bSrc + (size_t)(kt + i * 16) * N);
            CP_COMMIT();
            CP_WAIT(1);
        } else {
            CP_WAIT(0);
        }
        __syncthreads();

        const float* Ab = smem + buf * STAGE_F;
        const float* Bb = Ab + ABUF_F;
        int ar = (warpM << 5) + (lane >> 2);
        int bn = (warpN << 5) + (lane >> 2);
#pragma unroll
        for (int k8 = 0; k8 < 4; k8++) {
            uint32_t a[2][4], b[4][2];
            int ac = (k8 << 3) + (lane & 3);
            int bk = (k8 << 3) + (lane & 3);
#pragma unroll
            for (int mt = 0; mt < 2; mt++) {
                int r = ar + mt * 16;
                a[mt][0] = f2tf32(Ab[r * AS_STRIDE + ac]);
                a[mt][1] = f2tf32(Ab[(r + 8) * AS_STRIDE + ac]);
                a[mt][2] = f2tf32(Ab[r * AS_STRIDE + ac + 4]);
                a[mt][3] = f2tf32(Ab[(r + 8) * AS_STRIDE + ac + 4]);
            }
#pragma unroll
            for (int nt = 0; nt < 4; nt++) {
                b[nt][0] = f2tf32(Bb[bk * BS_STRIDE + bn + nt * 8]);
                b[nt][1] = f2tf32(Bb[(bk + 4) * BS_STRIDE + bn + nt * 8]);
            }
#pragma unroll
            for (int mt = 0; mt < 2; mt++)
#pragma unroll
                for (int nt = 0; nt < 4; nt++)
                    mma_tf32(acc[mt][nt], a[mt], b[nt]);
        }
        __syncthreads();
    }

    // ---------------- epilogue ----------------
    int rBase = rowBase + (warpM << 5) + (lane >> 2);
    int cBase = colBase + (warpN << 5) + ((lane & 3) << 1);
#pragma unroll
    for (int mt = 0; mt < 2; mt++) {
#pragma unroll
        for (int half = 0; half < 2; half++) {
            int m = rBase + mt * 16 + half * 8;
            int om = m;
            if (MODE == 1) om = orig_row(m);
#pragma unroll
            for (int nt = 0; nt < 4; nt++) {
#pragma unroll
                for (int j = 0; j < 2; j++) {
                    int n = cBase + nt * 8 + j;
                    float v = acc[mt][nt][half * 2 + j] + bias[n];
                    if (MODE == 0) {
                        if (n < DIM) v *= QSCALE;
                        g_qkv[(size_t)m * C3 + n] = v;
                    } else if (MODE == 1) {
                        g_x2[(size_t)om * DIM + n] = extra[(size_t)om * DIM + n] + v;
                    } else if (MODE == 2) {
                        g_mlp[(size_t)m * HID + n] =
                            0.5f * v * (1.0f + erff(v * 0.70710678118654752f));
                    } else {
                        outp[(size_t)m * DIM + n] = v + g_x2[(size_t)m * DIM + n];
                    }
                }
            }
        }
    }
}

// ---------------- attention: one block per (window, head) ----------------
// Scores in registers; smem only for q/k/v tiles (24 KB).
__global__ __launch_bounds__(64)
void attn_kernel() {
    __shared__ float sq[64 * 32];
    __shared__ float sk[64 * 32];
    __shared__ float sv[64 * 32];

    int win  = blockIdx.x / NHEAD;
    int head = blockIdx.x % NHEAD;
    int tid  = threadIdx.x;   // 0..63

    const float* base = g_qkv + (size_t)win * 64 * C3;
    int qoff = head * HD;
    int koff = DIM + head * HD;
    int voff = 2 * DIM + head * HD;

    for (int idx = tid; idx < 64 * 32; idx += 64) {
        int n = idx >> 5, d = idx & 31;
        sq[idx] = base[n * C3 + qoff + d];
        sk[idx] = base[n * C3 + koff + d];
        sv[idx] = base[n * C3 + voff + d];
    }
    __syncthreads();

    float qr[32];
#pragma unroll
    for (int d = 0; d < 32; d++) qr[d] = sq[tid * 32 + d];

    float s[64];
    float mx = -1e30f;
#pragma unroll
    for (int j = 0; j < 64; j++) {
        float acc = 0.f;
#pragma unroll
        for (int d = 0; d < 32; d++) acc = fmaf(qr[d], sk[j * 32 + d], acc);
        s[j] = acc;
        mx = fmaxf(mx, acc);
    }
    float sum = 0.f;
#pragma unroll
    for (int j = 0; j < 64; j++) {
        s[j] = __expf(s[j] - mx);
        sum += s[j];
    }
    float inv = 1.0f / sum;

    float o[32] = {};
#pragma unroll
    for (int j = 0; j < 64; j++) {
#pragma unroll
        for (int d = 0; d < 32; d++) o[d] = fmaf(s[j], sv[j * 32 + d], o[d]);
    }

    __syncthreads();
#pragma unroll
    for (int d = 0; d < 32; d++) sq[tid * 32 + d] = o[d] * inv;
    __syncthreads();

    float* obase = g_attn + (size_t)win * 64 * DIM + head * HD;
    for (int idx = tid; idx < 64 * 32; idx += 64) {
        int n = idx >> 5, d = idx & 31;
        obase[n * DIM + d] = sq[idx];
    }
}

// ---------------- launcher ----------------
extern "C" void kernel_launch(void* const* d_in, const int* in_sizes, int n_in,
                              void* d_out, int out_size) {
    const float* x       = (const float*)d_in[0];
    const float* norm1_g = (const float*)d_in[1];
    const float* norm1_b = (const float*)d_in[2];
    const float* qkv_w   = (const float*)d_in[3];
    const float* qkv_b   = (const float*)d_in[4];
    const float* proj_w  = (const float*)d_in[5];
    const float* proj_b  = (const float*)d_in[6];
    const float* norm2_g = (const float*)d_in[7];
    const float* norm2_b = (const float*)d_in[8];
    const float* fc1_w   = (const float*)d_in[9];
    const float* fc1_b   = (const float*)d_in[10];
    const float* fc2_w   = (const float*)d_in[11];
    const float* fc2_b   = (const float*)d_in[12];
    float* out = (float*)d_out;

    ln_kernel<false><<<MTOK / 8, 256>>>(x, norm1_g, norm1_b);
    gemm_tc<0, DIM, C3><<<dim3(C3 / 64, MTOK / 128), 256>>>(qkv_w, qkv_b, nullptr, nullptr);
    attn_kernel<<<NWIN * NHEAD, 64>>>();
    gemm_tc<1, DIM, DIM><<<dim3(DIM / 64, MTOK / 128), 256>>>(proj_w, proj_b, x, nullptr);
    ln_kernel<true><<<MTOK / 8, 256>>>(nullptr, norm2_g, norm2_b);
    gemm_tc<2, DIM, HID><<<dim3(HID / 64, MTOK / 128), 256>>>(fc1_w, fc1_b, nullptr, nullptr);
    gemm_tc<3, HID, DIM><<<dim3(DIM / 64, MTOK / 128), 256>>>(fc2_w, fc2_b, nullptr, out);
}